// round 2
// baseline (speedup 1.0000x reference)
#include <cuda_runtime.h>
#include <cstdint>

#define BATCH  32
#define NODES  20000
#define FEAT   64
#define OUTF   64
#define EIG    16

#define NCHUNK 20
#define MCHUNK (NODES / NCHUNK)   // 1000
#define K1TILE 128

#define NCH3   125                // k3 grid.x
#define NPB3   160                // nodes per k3 block (32 rows x TN3)
#define TN3    5

typedef unsigned long long ull;

// Scratch (device globals; no allocation allowed)
__device__ __align__(16) float zpart_g[BATCH * NCHUNK * FEAT * EIG]; // 2.6 MB
__device__ __align__(16) float z_g[BATCH * FEAT * EIG];              // 128 KB
__device__ __align__(16) float w_g[BATCH * OUTF * EIG];              // 128 KB

// ---- packed f32x2 helpers (Blackwell-only; ptxas won't auto-fuse) ----
__device__ __forceinline__ ull ffma2(ull a, ull b, ull c) {
    ull d;
    asm("fma.rn.f32x2 %0, %1, %2, %3;" : "=l"(d) : "l"(a), "l"(b), "l"(c));
    return d;
}
__device__ __forceinline__ ull fadd2(ull a, ull b) {
    ull d;
    asm("add.rn.f32x2 %0, %1, %2;" : "=l"(d) : "l"(a), "l"(b));
    return d;
}
__device__ __forceinline__ ull pack2(float x) {
    ull d;
    asm("mov.b64 %0, {%1, %1};" : "=l"(d) : "f"(x));
    return d;
}

// ============================================================================
// Kernel 1: zpart[b][chunk][i][e] = sum_{m in chunk} V[m,e] * x[b,m,i]
// grid (NCHUNK, BATCH), 256 thr: il = i-group of 4 (0..15), mr = m-row (0..15)
// Thread tile: 4 i's x 16 e's. Per node: 1 LDG.128 (x) + 64B LDS (V, shared
// across the 4 i's) + 32 FFMA2.
// ============================================================================
__global__ void __launch_bounds__(256, 2) k1_project(const float* __restrict__ x,
                                                     const float* __restrict__ V) {
    __shared__ ulonglong2 Vs[K1TILE][4];      // V rows as f32x2 pairs, 8 KB
    __shared__ ull red[8][16][32];            // tree-reduction buffer, 32 KB

    const int tid = threadIdx.x;
    const int il  = tid & 15;                 // i = il*4 + ii
    const int mr  = tid >> 4;                 // 0..15
    const int b   = blockIdx.y;
    const int m0  = blockIdx.x * MCHUNK;

    const float4* xb = (const float4*)(x + ((size_t)b * NODES + m0) * FEAT);

    ull acc[4][8];
#pragma unroll
    for (int ii = 0; ii < 4; ++ii)
#pragma unroll
        for (int p = 0; p < 8; ++p) acc[ii][p] = 0ULL;

    for (int tbase = 0; tbase < MCHUNK; tbase += K1TILE) {
        int valid = MCHUNK - tbase;
        if (valid > K1TILE) valid = K1TILE;

        // cooperative V tile load (coalesced 16B)
        for (int idx = tid; idx < K1TILE * 4; idx += 256) {
            int ml = idx >> 2, p = idx & 3;
            ulonglong2 v = make_ulonglong2(0ULL, 0ULL);
            if (ml < valid)
                v = ((const ulonglong2*)(V + (size_t)(m0 + tbase + ml) * EIG))[p];
            Vs[ml][p] = v;
        }
        __syncthreads();

        if (valid == K1TILE) {
#pragma unroll
            for (int t = 0; t < K1TILE / 16; ++t) {
                int ml = mr + t * 16;
                float4 xv = xb[(size_t)(tbase + ml) * 16 + il];
                ull xp[4] = { pack2(xv.x), pack2(xv.y), pack2(xv.z), pack2(xv.w) };
                ulonglong2 q0 = Vs[ml][0], q1 = Vs[ml][1], q2 = Vs[ml][2], q3 = Vs[ml][3];
                ull v[8] = { q0.x, q0.y, q1.x, q1.y, q2.x, q2.y, q3.x, q3.y };
#pragma unroll
                for (int ii = 0; ii < 4; ++ii)
#pragma unroll
                    for (int p = 0; p < 8; ++p)
                        acc[ii][p] = ffma2(v[p], xp[ii], acc[ii][p]);
            }
        } else {
            for (int ml = mr; ml < valid; ml += 16) {
                float4 xv = xb[(size_t)(tbase + ml) * 16 + il];
                ull xp[4] = { pack2(xv.x), pack2(xv.y), pack2(xv.z), pack2(xv.w) };
                ulonglong2 q0 = Vs[ml][0], q1 = Vs[ml][1], q2 = Vs[ml][2], q3 = Vs[ml][3];
                ull v[8] = { q0.x, q0.y, q1.x, q1.y, q2.x, q2.y, q3.x, q3.y };
#pragma unroll
                for (int ii = 0; ii < 4; ++ii)
#pragma unroll
                    for (int p = 0; p < 8; ++p)
                        acc[ii][p] = ffma2(v[p], xp[ii], acc[ii][p]);
            }
        }
        __syncthreads();
    }

    // deterministic 4-round tree reduction across the 16 mr rows
#pragma unroll
    for (int off = 8; off >= 1; off >>= 1) {
        if (mr >= off && mr < 2 * off) {
            ull* dst = red[mr - off][il];
#pragma unroll
            for (int ii = 0; ii < 4; ++ii)
#pragma unroll
                for (int p = 0; p < 8; ++p) dst[ii * 8 + p] = acc[ii][p];
        }
        __syncthreads();
        if (mr < off) {
            const ull* src = red[mr][il];
#pragma unroll
            for (int ii = 0; ii < 4; ++ii)
#pragma unroll
                for (int p = 0; p < 8; ++p)
                    acc[ii][p] = fadd2(acc[ii][p], src[ii * 8 + p]);
        }
        __syncthreads();
    }

    if (mr == 0) {
        ull* zp = (ull*)(zpart_g + ((size_t)b * NCHUNK + blockIdx.x) * (FEAT * EIG));
#pragma unroll
        for (int ii = 0; ii < 4; ++ii)
#pragma unroll
            for (int p = 0; p < 8; ++p)
                zp[(size_t)(il * 4 + ii) * 8 + p] = acc[ii][p];
    }
}

// ============================================================================
// Kernel 1b: z[b][i][e] = sum_c zpart[b][c][i][e]      grid 32 x 256
// ============================================================================
__global__ void __launch_bounds__(256) k1b_reduce() {
    int idx = blockIdx.x * 256 + threadIdx.x;  // 0..8191 float4 slots
    int b = idx >> 8, q = idx & 255;
    const float4* zp = (const float4*)zpart_g;
    float4 s = make_float4(0.f, 0.f, 0.f, 0.f);
#pragma unroll
    for (int c = 0; c < NCHUNK; ++c) {
        float4 v = zp[((size_t)b * NCHUNK + c) * 256 + q];
        s.x += v.x; s.y += v.y; s.z += v.z; s.w += v.w;
    }
    ((float4*)z_g)[(size_t)b * 256 + q] = s;
}

// ============================================================================
// Kernel 2: w[b][j][e] = sum_{i,f} G[j,i,e,f] * z[b,i,f]
// One warp per (c = j*16+e, batch-group of 8).  grid 512 x 256
// ============================================================================
__global__ void __launch_bounds__(256) k2_mix(const float* __restrict__ G) {
    const int lane = threadIdx.x & 31;
    const int W    = blockIdx.x * 8 + (threadIdx.x >> 5);
    const int c    = W >> 2;
    const int bg   = W & 3;
    const int j    = c >> 4;
    const int e    = c & 15;

    const float4* Gp = (const float4*)(G + (size_t)j * (FEAT * EIG * EIG) + (size_t)e * EIG);
    const float4* zb = (const float4*)z_g;
    const int i0 = lane >> 2, fq = lane & 3;

    float acc[8];
#pragma unroll
    for (int r = 0; r < 8; ++r) acc[r] = 0.f;

#pragma unroll
    for (int s = 0; s < 8; ++s) {
        int i  = s * 8 + i0;
        float4 g = Gp[(size_t)i * 64 + fq];
        int kq = i * 4 + fq;
#pragma unroll
        for (int r = 0; r < 8; ++r) {
            float4 zv = zb[(size_t)(bg * 8 + r) * 256 + kq];
            acc[r] = fmaf(g.x, zv.x, fmaf(g.y, zv.y, fmaf(g.z, zv.z, fmaf(g.w, zv.w, acc[r]))));
        }
    }
#pragma unroll
    for (int r = 0; r < 8; ++r) {
#pragma unroll
        for (int off = 16; off; off >>= 1)
            acc[r] += __shfl_xor_sync(0xffffffffu, acc[r], off);
    }
    if (lane == 0) {
#pragma unroll
        for (int r = 0; r < 8; ++r)
            w_g[(size_t)(bg * 8 + r) * 1024 + c] = acc[r];
    }
}

// ============================================================================
// Kernel 3: out[b,n,j] = sum_e V[n,e] * w[b,j,e]
// grid (NCH3, BATCH), 256 thr: jl = j-group of 8 (0..7), nr = node row (0..31)
// Thread tile: 5 nodes x 8 j's. V from global into registers; w transposed
// into 4KB smem, read 32B per e, shared across the 5 nodes.
// ============================================================================
__global__ void __launch_bounds__(256, 2) k3_expand(const float* __restrict__ V,
                                                    float* __restrict__ out) {
    __shared__ float wsm[EIG][OUTF];   // wsm[e][j], 4 KB

    const int tid = threadIdx.x;
    const int jl  = tid & 7;           // j = jl*8 .. jl*8+7
    const int nr  = tid >> 3;          // 0..31
    const int b   = blockIdx.y;
    const int n0  = blockIdx.x * NPB3;

    // stage w transposed: wsm[e][j] = w_g[b][j][e]
    for (int idx = tid; idx < OUTF * EIG; idx += 256) {
        int j = idx >> 4, e = idx & 15;
        wsm[e][j] = w_g[(size_t)b * (OUTF * EIG) + idx];
    }
    __syncthreads();

    ull acc[TN3][4];
#pragma unroll
    for (int k = 0; k < TN3; ++k)
#pragma unroll
        for (int p = 0; p < 4; ++p) acc[k][p] = 0ULL;

    const int nb = n0 + nr;            // nodes: nb + 32*k

#pragma unroll
    for (int eb = 0; eb < 4; ++eb) {
        float va[TN3][4];
#pragma unroll
        for (int k = 0; k < TN3; ++k) {
            float4 v4 = ((const float4*)(V + (size_t)(nb + 32 * k) * EIG))[eb];
            va[k][0] = v4.x; va[k][1] = v4.y; va[k][2] = v4.z; va[k][3] = v4.w;
        }
#pragma unroll
        for (int e2 = 0; e2 < 4; ++e2) {
            int e = eb * 4 + e2;
            const ull* w2 = (const ull*)&wsm[e][jl * 8];
            ull wv0 = w2[0], wv1 = w2[1], wv2 = w2[2], wv3 = w2[3];
#pragma unroll
            for (int k = 0; k < TN3; ++k) {
                ull vp = pack2(va[k][e2]);
                acc[k][0] = ffma2(wv0, vp, acc[k][0]);
                acc[k][1] = ffma2(wv1, vp, acc[k][1]);
                acc[k][2] = ffma2(wv2, vp, acc[k][2]);
                acc[k][3] = ffma2(wv3, vp, acc[k][3]);
            }
        }
    }

#pragma unroll
    for (int k = 0; k < TN3; ++k) {
        int n = nb + 32 * k;
        ulonglong2* op = (ulonglong2*)(out + ((size_t)b * NODES + n) * OUTF + jl * 8);
        op[0] = make_ulonglong2(acc[k][0], acc[k][1]);
        op[1] = make_ulonglong2(acc[k][2], acc[k][3]);
    }
}

// ============================================================================
extern "C" void kernel_launch(void* const* d_in, const int* in_sizes, int n_in,
                              void* d_out, int out_size) {
    const float* x = (const float*)d_in[0];   // (32, 20000, 64)
    const float* V = (const float*)d_in[1];   // (20000, 16)
    const float* G = (const float*)d_in[2];   // (64, 64, 16, 16)
    float* out = (float*)d_out;               // (32, 20000, 64)

    k1_project<<<dim3(NCHUNK, BATCH), 256>>>(x, V);
    k1b_reduce<<<32, 256>>>();
    k2_mix<<<512, 256>>>(G);
    k3_expand<<<dim3(NCH3, BATCH), 256>>>(V, out);
}

// round 4
// speedup vs baseline: 1.2737x; 1.2737x over previous
#include <cuda_runtime.h>
#include <cstdint>

#define BATCH  32
#define NODES  20000
#define FEAT   64
#define OUTF   64
#define EIG    16

#define NCHUNK 25
#define MCHUNK (NODES / NCHUNK)   // 800
#define K1TILE 160                // V rows staged per k1 tile

#define NPB3   160                // nodes per k3 block
#define NCH3   (NODES / NPB3)     // 125

typedef unsigned long long ull;

// Scratch (device globals; no allocation allowed)
__device__ __align__(16) float zpart_g[BATCH * NCHUNK * FEAT * EIG]; // 3.3 MB
__device__ __align__(16) float z_g[BATCH * FEAT * EIG];              // 128 KB
__device__ __align__(16) float w_g[BATCH * OUTF * EIG];              // 128 KB

// ---- packed f32x2 helpers ----
__device__ __forceinline__ ull ffma2(ull a, ull b, ull c) {
    ull d;
    asm("fma.rn.f32x2 %0, %1, %2, %3;" : "=l"(d) : "l"(a), "l"(b), "l"(c));
    return d;
}
__device__ __forceinline__ ull fadd2(ull a, ull b) {
    ull d;
    asm("add.rn.f32x2 %0, %1, %2;" : "=l"(d) : "l"(a), "l"(b));
    return d;
}
__device__ __forceinline__ ull pack2(float x) {
    ull d;
    asm("mov.b64 %0, {%1, %1};" : "=l"(d) : "f"(x));
    return d;
}
__device__ __forceinline__ ull packab(float a, float b) {
    ull d;
    asm("mov.b64 %0, {%1, %2};" : "=l"(d) : "f"(a), "f"(b));
    return d;
}

// ============================================================================
// Kernel 1: zpart[b][chunk][i][e] = sum_{m in chunk} V[m,e] * x[b,m,i]
// grid (NCHUNK, BATCH), 256 thr = 8 warps. Warp w owns nodes w+8t of each tile;
// lane l owns i = 2l, 2l+1 (acc packed over e-pairs, 16 f32x2 regs).
// Per node/warp: 1 LDG.64 (x, coalesced 256B/warp) + 4 LDS.128 (V broadcast)
//                + 2 pack2 + 16 FFMA2.
// ============================================================================
__global__ void __launch_bounds__(256, 3) k1_project(const float* __restrict__ x,
                                                     const float* __restrict__ V) {
    __shared__ __align__(16) ulonglong2 Vs[K1TILE][4];   // 10 KB
    __shared__ __align__(16) ull part[8][32][16];        // 32 KB

    const int tid  = threadIdx.x;
    const int lane = tid & 31;
    const int w    = tid >> 5;
    const int b    = blockIdx.y;
    const int m0   = blockIdx.x * MCHUNK;

    const float2* xb = (const float2*)(x + ((size_t)b * NODES + m0) * FEAT) + lane;

    ull acc[16];
#pragma unroll
    for (int p = 0; p < 16; ++p) acc[p] = 0ULL;

#pragma unroll 1
    for (int tb = 0; tb < MCHUNK; tb += K1TILE) {
        // stage V tile (coalesced 16B loads)
        for (int idx = tid; idx < K1TILE * 4; idx += 256) {
            int ml = idx >> 2, p = idx & 3;
            Vs[ml][p] = ((const ulonglong2*)(V + (size_t)(m0 + tb + ml) * EIG))[p];
        }
        __syncthreads();

#pragma unroll 1
        for (int t = 0; t < K1TILE / 8; t += 4) {
            float2 xv[4];
#pragma unroll
            for (int k = 0; k < 4; ++k)
                xv[k] = xb[(size_t)(tb + w + 8 * (t + k)) * 32];
#pragma unroll
            for (int k = 0; k < 4; ++k) {
                const int ml = w + 8 * (t + k);
                ull xa = pack2(xv[k].x);
                ull xc = pack2(xv[k].y);
                ulonglong2 q0 = Vs[ml][0], q1 = Vs[ml][1], q2 = Vs[ml][2], q3 = Vs[ml][3];
                acc[0]  = ffma2(q0.x, xa, acc[0]);
                acc[1]  = ffma2(q0.y, xa, acc[1]);
                acc[2]  = ffma2(q1.x, xa, acc[2]);
                acc[3]  = ffma2(q1.y, xa, acc[3]);
                acc[4]  = ffma2(q2.x, xa, acc[4]);
                acc[5]  = ffma2(q2.y, xa, acc[5]);
                acc[6]  = ffma2(q3.x, xa, acc[6]);
                acc[7]  = ffma2(q3.y, xa, acc[7]);
                acc[8]  = ffma2(q0.x, xc, acc[8]);
                acc[9]  = ffma2(q0.y, xc, acc[9]);
                acc[10] = ffma2(q1.x, xc, acc[10]);
                acc[11] = ffma2(q1.y, xc, acc[11]);
                acc[12] = ffma2(q2.x, xc, acc[12]);
                acc[13] = ffma2(q2.y, xc, acc[13]);
                acc[14] = ffma2(q3.x, xc, acc[14]);
                acc[15] = ffma2(q3.y, xc, acc[15]);
            }
        }
        __syncthreads();
    }

    // dump per-warp partials, then flat deterministic sum over the 8 warps
#pragma unroll
    for (int p = 0; p < 16; ++p) part[w][lane][p] = acc[p];
    __syncthreads();

    {
        const int li = tid >> 3;            // ull-slot pair (2*tid, 2*tid+1)
        const int k  = (2 * tid) & 15;
        ulonglong2 r = *(const ulonglong2*)&part[0][li][k];
#pragma unroll
        for (int ww = 1; ww < 8; ++ww) {
            ulonglong2 s = *(const ulonglong2*)&part[ww][li][k];
            r.x = fadd2(r.x, s.x);
            r.y = fadd2(r.y, s.y);
        }
        ulonglong2* zp = (ulonglong2*)(zpart_g + ((size_t)b * NCHUNK + blockIdx.x) * (FEAT * EIG));
        zp[tid] = r;
    }
}

// ============================================================================
// Kernel 1b: z[b][i][e] = sum_c zpart[b][c][i][e]      grid 32 x 256
// ============================================================================
__global__ void __launch_bounds__(256) k1b_reduce() {
    int idx = blockIdx.x * 256 + threadIdx.x;
    int b = idx >> 8, q = idx & 255;
    const float4* zp = (const float4*)zpart_g;
    float4 s = make_float4(0.f, 0.f, 0.f, 0.f);
#pragma unroll
    for (int c = 0; c < NCHUNK; ++c) {
        float4 v = zp[((size_t)b * NCHUNK + c) * 256 + q];
        s.x += v.x; s.y += v.y; s.z += v.z; s.w += v.w;
    }
    ((float4*)z_g)[(size_t)b * 256 + q] = s;
}

// ============================================================================
// Kernel 2: w[b][j][e] = sum_{i,f} G[j,i,e,f] * z[b,i,f]
// One warp per (c = j*16+e, batch-group of 8).  grid 512 x 256
// ============================================================================
__global__ void __launch_bounds__(256) k2_mix(const float* __restrict__ G) {
    const int lane = threadIdx.x & 31;
    const int W    = blockIdx.x * 8 + (threadIdx.x >> 5);
    const int c    = W >> 2;
    const int bg   = W & 3;
    const int j    = c >> 4;
    const int e    = c & 15;

    const float4* Gp = (const float4*)(G + (size_t)j * (FEAT * EIG * EIG) + (size_t)e * EIG);
    const float4* zb = (const float4*)z_g;
    const int i0 = lane >> 2, fq = lane & 3;

    float acc[8];
#pragma unroll
    for (int r = 0; r < 8; ++r) acc[r] = 0.f;

#pragma unroll
    for (int s = 0; s < 8; ++s) {
        int i  = s * 8 + i0;
        float4 g = Gp[(size_t)i * 64 + fq];
        int kq = i * 4 + fq;
#pragma unroll
        for (int r = 0; r < 8; ++r) {
            float4 zv = zb[(size_t)(bg * 8 + r) * 256 + kq];
            acc[r] = fmaf(g.x, zv.x, fmaf(g.y, zv.y, fmaf(g.z, zv.z, fmaf(g.w, zv.w, acc[r]))));
        }
    }
#pragma unroll
    for (int r = 0; r < 8; ++r) {
#pragma unroll
        for (int off = 16; off; off >>= 1)
            acc[r] += __shfl_xor_sync(0xffffffffu, acc[r], off);
    }
    if (lane == 0) {
#pragma unroll
        for (int r = 0; r < 8; ++r)
            w_g[(size_t)(bg * 8 + r) * 1024 + c] = acc[r];
    }
}

// ============================================================================
// Kernel 3: out[b,n,j] = sum_e V[n,e] * w[b,j,e]
// grid (NCH3, BATCH), 256 thr = 8 warps. Warp w owns nodes n0+w+8t;
// lane l owns j-pair (2l, 2l+1); w[j-pair][e] held in 16 f32x2 regs.
// V staged in smem PRE-DUPLICATED as f32x2 -> no per-FMA pack2.
// Per node/warp: 8 LDS.128 (broadcast) + 16 FFMA2 + 1 fadd2 + 1 STG.64.
// ============================================================================
__global__ void __launch_bounds__(256, 3) k3_expand(const float* __restrict__ V,
                                                    float* __restrict__ out) {
    __shared__ __align__(16) ull Vdup[NPB3][16];   // 20 KB
    __shared__ float wsm[OUTF * 17];               // padded rows, 4.25 KB

    const int tid  = threadIdx.x;
    const int lane = tid & 31;
    const int w    = tid >> 5;
    const int b    = blockIdx.y;
    const int n0   = blockIdx.x * NPB3;

    // stage w[b] with row padding 17 (bank-conflict-free transpose reads)
    for (int idx = tid; idx < OUTF * EIG; idx += 256) {
        int j = idx >> 4, e = idx & 15;
        wsm[j * 17 + e] = w_g[(size_t)b * (OUTF * EIG) + idx];
    }
    // stage V rows duplicated: Vdup[nl][e] = (V[n,e], V[n,e])
    for (int idx = tid; idx < NPB3 * EIG; idx += 256) {
        float v = V[(size_t)n0 * EIG + idx];   // idx = nl*16 + e (contiguous)
        Vdup[idx >> 4][idx & 15] = pack2(v);
    }
    __syncthreads();

    // per-lane w registers packed over the j-pair
    ull wreg[16];
#pragma unroll
    for (int e = 0; e < 16; ++e)
        wreg[e] = packab(wsm[lane * 34 + e], wsm[lane * 34 + 17 + e]);

    float* ob = out + ((size_t)b * NODES + n0) * OUTF + 2 * lane;

#pragma unroll 1
    for (int t = 0; t < NPB3 / 8; t += 4) {
        ull res[4];
#pragma unroll
        for (int k = 0; k < 4; ++k) {
            const int nl = w + 8 * (t + k);
            const ulonglong2* vd = (const ulonglong2*)Vdup[nl];
            ulonglong2 v0 = vd[0], v1 = vd[1], v2 = vd[2], v3 = vd[3];
            ull a = ffma2(wreg[0], v0.x, 0ULL);
            ull c = ffma2(wreg[1], v0.y, 0ULL);
            a = ffma2(wreg[2], v1.x, a);
            c = ffma2(wreg[3], v1.y, c);
            a = ffma2(wreg[4], v2.x, a);
            c = ffma2(wreg[5], v2.y, c);
            a = ffma2(wreg[6], v3.x, a);
            c = ffma2(wreg[7], v3.y, c);
            ulonglong2 v4 = vd[4], v5 = vd[5], v6 = vd[6], v7 = vd[7];
            a = ffma2(wreg[8],  v4.x, a);
            c = ffma2(wreg[9],  v4.y, c);
            a = ffma2(wreg[10], v5.x, a);
            c = ffma2(wreg[11], v5.y, c);
            a = ffma2(wreg[12], v6.x, a);
            c = ffma2(wreg[13], v6.y, c);
            a = ffma2(wreg[14], v7.x, a);
            c = ffma2(wreg[15], v7.y, c);
            res[k] = fadd2(a, c);
        }
#pragma unroll
        for (int k = 0; k < 4; ++k) {
            const int nl = w + 8 * (t + k);
            *(ull*)(ob + (size_t)nl * OUTF) = res[k];
        }
    }
}

// ============================================================================
extern "C" void kernel_launch(void* const* d_in, const int* in_sizes, int n_in,
                              void* d_out, int out_size) {
    const float* x = (const float*)d_in[0];   // (32, 20000, 64)
    const float* V = (const float*)d_in[1];   // (20000, 16)
    const float* G = (const float*)d_in[2];   // (64, 64, 16, 16)
    float* out = (float*)d_out;               // (32, 20000, 64)

    k1_project<<<dim3(NCHUNK, BATCH), 256>>>(x, V);
    k1b_reduce<<<32, 256>>>();
    k2_mix<<<512, 256>>>(G);
    k3_expand<<<dim3(NCH3, BATCH), 256>>>(V, out);
}

// round 5
// speedup vs baseline: 1.5742x; 1.2360x over previous
#include <cuda_runtime.h>
#include <cstdint>

#define BATCH  32
#define NODES  20000
#define FEAT   64
#define OUTF   64
#define EIG    16

#define NCHUNK 25
#define MCHUNK (NODES / NCHUNK)   // 800
#define K1TILE 160                // V rows staged per k1 tile (5 tiles/chunk)
#define STRIP  (K1TILE / 8)       // 20 contiguous rows per warp per tile

#define NPB3   160                // nodes per k3 block
#define NCH3   (NODES / NPB3)     // 125

typedef unsigned long long ull;

// Scratch (device globals; no allocation allowed)
__device__ __align__(16) float zpart_g[BATCH * NCHUNK * FEAT * EIG]; // 3.3 MB
__device__ __align__(16) float z_g[BATCH * FEAT * EIG];              // 128 KB
__device__ __align__(16) float w_g[BATCH * OUTF * EIG];              // 128 KB

// ---- packed f32x2 helpers ----
__device__ __forceinline__ ull ffma2(ull a, ull b, ull c) {
    ull d;
    asm("fma.rn.f32x2 %0, %1, %2, %3;" : "=l"(d) : "l"(a), "l"(b), "l"(c));
    return d;
}
__device__ __forceinline__ ull fadd2(ull a, ull b) {
    ull d;
    asm("add.rn.f32x2 %0, %1, %2;" : "=l"(d) : "l"(a), "l"(b));
    return d;
}
__device__ __forceinline__ ull pack2(float x) {
    ull d;
    asm("mov.b64 %0, {%1, %1};" : "=l"(d) : "f"(x));
    return d;
}
__device__ __forceinline__ ull packab(float a, float b) {
    ull d;
    asm("mov.b64 %0, {%1, %2};" : "=l"(d) : "f"(a), "f"(b));
    return d;
}
__device__ __forceinline__ float hsum2(ull a) {
    float lo, hi;
    asm("mov.b64 {%0, %1}, %2;" : "=f"(lo), "=f"(hi) : "l"(a));
    return lo + hi;
}

// ============================================================================
// Kernel 1: zpart[b][chunk][i][e] = sum_{m in chunk} V[m,e] * x[b,m,i]
// grid (NCHUNK, BATCH), 256 thr = 8 warps. Warp w owns a contiguous STRIP of
// rows per tile; lane l owns i = 2l,2l+1; acc packed over e-pairs (16 f32x2).
// x loads batched 10-deep for MLP (LDG.64, 256 B/warp coalesced).
// ============================================================================
__global__ void __launch_bounds__(256, 3) k1_project(const float* __restrict__ x,
                                                     const float* __restrict__ V) {
    __shared__ __align__(16) ulonglong2 Vs[K1TILE][4];   // 10 KB
    __shared__ __align__(16) ull part[8][32][16];        // 32 KB

    const int tid  = threadIdx.x;
    const int lane = tid & 31;
    const int w    = tid >> 5;
    const int b    = blockIdx.y;
    const int m0   = blockIdx.x * MCHUNK;

    const float2* xb = (const float2*)(x + ((size_t)b * NODES + m0) * FEAT) + lane;

    ull acc[16];
#pragma unroll
    for (int p = 0; p < 16; ++p) acc[p] = 0ULL;

#pragma unroll 1
    for (int tb = 0; tb < MCHUNK; tb += K1TILE) {
        // stage V tile (coalesced 16B loads)
        for (int idx = tid; idx < K1TILE * 4; idx += 256) {
            int ml = idx >> 2, p = idx & 3;
            Vs[ml][p] = ((const ulonglong2*)(V + (size_t)(m0 + tb + ml) * EIG))[p];
        }
        __syncthreads();

        const int r0 = tb + w * STRIP;
#pragma unroll 1
        for (int half = 0; half < 2; ++half) {
            float2 xv[10];
#pragma unroll
            for (int k = 0; k < 10; ++k)
                xv[k] = xb[(size_t)(r0 + half * 10 + k) * 32];
#pragma unroll
            for (int k = 0; k < 10; ++k) {
                const int ml = w * STRIP + half * 10 + k;
                ull xa = pack2(xv[k].x);
                ull xc = pack2(xv[k].y);
                ulonglong2 q0 = Vs[ml][0], q1 = Vs[ml][1], q2 = Vs[ml][2], q3 = Vs[ml][3];
                acc[0]  = ffma2(q0.x, xa, acc[0]);
                acc[1]  = ffma2(q0.y, xa, acc[1]);
                acc[2]  = ffma2(q1.x, xa, acc[2]);
                acc[3]  = ffma2(q1.y, xa, acc[3]);
                acc[4]  = ffma2(q2.x, xa, acc[4]);
                acc[5]  = ffma2(q2.y, xa, acc[5]);
                acc[6]  = ffma2(q3.x, xa, acc[6]);
                acc[7]  = ffma2(q3.y, xa, acc[7]);
                acc[8]  = ffma2(q0.x, xc, acc[8]);
                acc[9]  = ffma2(q0.y, xc, acc[9]);
                acc[10] = ffma2(q1.x, xc, acc[10]);
                acc[11] = ffma2(q1.y, xc, acc[11]);
                acc[12] = ffma2(q2.x, xc, acc[12]);
                acc[13] = ffma2(q2.y, xc, acc[13]);
                acc[14] = ffma2(q3.x, xc, acc[14]);
                acc[15] = ffma2(q3.y, xc, acc[15]);
            }
        }
        __syncthreads();
    }

    // dump per-warp partials, then flat deterministic sum over the 8 warps
#pragma unroll
    for (int p = 0; p < 16; ++p) part[w][lane][p] = acc[p];
    __syncthreads();

    {
        const int li = tid >> 3;            // ull-slot pair (2*tid, 2*tid+1)
        const int k  = (2 * tid) & 15;
        ulonglong2 r = *(const ulonglong2*)&part[0][li][k];
#pragma unroll
        for (int ww = 1; ww < 8; ++ww) {
            ulonglong2 s = *(const ulonglong2*)&part[ww][li][k];
            r.x = fadd2(r.x, s.x);
            r.y = fadd2(r.y, s.y);
        }
        ulonglong2* zp = (ulonglong2*)(zpart_g + ((size_t)b * NCHUNK + blockIdx.x) * (FEAT * EIG));
        zp[tid] = r;
    }
}

// ============================================================================
// Kernel 1b: z[b][i][e] = sum_c zpart[b][c][i][e]      grid 32 x 256
// ============================================================================
__global__ void __launch_bounds__(256) k1b_reduce() {
    int idx = blockIdx.x * 256 + threadIdx.x;
    int b = idx >> 8, q = idx & 255;
    const float4* zp = (const float4*)zpart_g;
    float4 s = make_float4(0.f, 0.f, 0.f, 0.f);
#pragma unroll
    for (int c = 0; c < NCHUNK; ++c) {
        float4 v = zp[((size_t)b * NCHUNK + c) * 256 + q];
        s.x += v.x; s.y += v.y; s.z += v.z; s.w += v.w;
    }
    ((float4*)z_g)[(size_t)b * 256 + q] = s;
}

// ============================================================================
// Kernel 2: w[b][j][e] = sum_{i,f} G[j,i,e,f] * z[b,i,f]
// One warp per (c = j*16+e, batch-group of 8).  grid 512 x 256
// ============================================================================
__global__ void __launch_bounds__(256) k2_mix(const float* __restrict__ G) {
    const int lane = threadIdx.x & 31;
    const int W    = blockIdx.x * 8 + (threadIdx.x >> 5);
    const int c    = W >> 2;
    const int bg   = W & 3;
    const int j    = c >> 4;
    const int e    = c & 15;

    const float4* Gp = (const float4*)(G + (size_t)j * (FEAT * EIG * EIG) + (size_t)e * EIG);
    const float4* zb = (const float4*)z_g;
    const int i0 = lane >> 2, fq = lane & 3;

    float acc[8];
#pragma unroll
    for (int r = 0; r < 8; ++r) acc[r] = 0.f;

#pragma unroll
    for (int s = 0; s < 8; ++s) {
        int i  = s * 8 + i0;
        float4 g = Gp[(size_t)i * 64 + fq];
        int kq = i * 4 + fq;
#pragma unroll
        for (int r = 0; r < 8; ++r) {
            float4 zv = zb[(size_t)(bg * 8 + r) * 256 + kq];
            acc[r] = fmaf(g.x, zv.x, fmaf(g.y, zv.y, fmaf(g.z, zv.z, fmaf(g.w, zv.w, acc[r]))));
        }
    }
#pragma unroll
    for (int r = 0; r < 8; ++r) {
#pragma unroll
        for (int off = 16; off; off >>= 1)
            acc[r] += __shfl_xor_sync(0xffffffffu, acc[r], off);
    }
    if (lane == 0) {
#pragma unroll
        for (int r = 0; r < 8; ++r)
            w_g[(size_t)(bg * 8 + r) * 1024 + c] = acc[r];
    }
}

// ============================================================================
// Kernel 3: out[b,n,j] = sum_e V[n,e] * w[b,j,e]
// grid (NCH3, BATCH), 256 thr = 8 warps. Warp w owns nodes n0+w+8t;
// lane l owns j = l and j = l+32. Accumulate packed over e-PAIRS, so V is
// staged NON-duplicated: 4 LDS.128 per node (was 8). Final hsum2 per j.
// Per node/warp: 4 LDS.128 + 16 FFMA2 + 2 fadd2 + 2 hsum + 2 STG.32 (coalesced).
// ============================================================================
__global__ void __launch_bounds__(256, 4) k3_expand(const float* __restrict__ V,
                                                    float* __restrict__ out) {
    __shared__ __align__(16) ull Vp[NPB3][8];      // (V[e],V[e+1]) pairs, 10 KB
    __shared__ float wsm[OUTF * 17];               // padded rows, 4.25 KB

    const int tid  = threadIdx.x;
    const int lane = tid & 31;
    const int w    = tid >> 5;
    const int b    = blockIdx.y;
    const int n0   = blockIdx.x * NPB3;

    // stage w[b] with row padding 17 (bank-conflict-free scalar reads)
    for (int idx = tid; idx < OUTF * EIG; idx += 256) {
        int j = idx >> 4, e = idx & 15;
        wsm[j * 17 + e] = w_g[(size_t)b * (OUTF * EIG) + idx];
    }
    // stage V rows as natural f32x2 pairs (plain contiguous copy, 16B loads)
    for (int idx = tid; idx < NPB3 * 4; idx += 256) {
        ((ulonglong2*)Vp)[idx] = ((const ulonglong2*)(V + (size_t)n0 * EIG))[idx];
    }
    __syncthreads();

    // per-lane w registers packed over e-pairs, for j=lane and j=lane+32
    ull wra[8], wrb[8];
#pragma unroll
    for (int p = 0; p < 8; ++p) {
        wra[p] = packab(wsm[lane * 17 + 2 * p], wsm[lane * 17 + 2 * p + 1]);
        wrb[p] = packab(wsm[(lane + 32) * 17 + 2 * p], wsm[(lane + 32) * 17 + 2 * p + 1]);
    }

    float* ob = out + ((size_t)b * NODES + n0) * OUTF + lane;

#pragma unroll 1
    for (int t = 0; t < NPB3 / 8; t += 2) {
        float resA[2], resB[2];
#pragma unroll
        for (int k = 0; k < 2; ++k) {
            const int nl = w + 8 * (t + k);
            const ulonglong2* vd = (const ulonglong2*)Vp[nl];
            ulonglong2 p0 = vd[0], p1 = vd[1], p2 = vd[2], p3 = vd[3];
            ull a = ffma2(p0.x, wra[0], 0ULL);
            ull c = ffma2(p0.y, wra[1], 0ULL);
            a = ffma2(p1.x, wra[2], a);
            c = ffma2(p1.y, wra[3], c);
            a = ffma2(p2.x, wra[4], a);
            c = ffma2(p2.y, wra[5], c);
            a = ffma2(p3.x, wra[6], a);
            c = ffma2(p3.y, wra[7], c);
            resA[k] = hsum2(fadd2(a, c));
            ull a2 = ffma2(p0.x, wrb[0], 0ULL);
            ull c2 = ffma2(p0.y, wrb[1], 0ULL);
            a2 = ffma2(p1.x, wrb[2], a2);
            c2 = ffma2(p1.y, wrb[3], c2);
            a2 = ffma2(p2.x, wrb[4], a2);
            c2 = ffma2(p2.y, wrb[5], c2);
            a2 = ffma2(p3.x, wrb[6], a2);
            c2 = ffma2(p3.y, wrb[7], c2);
            resB[k] = hsum2(fadd2(a2, c2));
        }
#pragma unroll
        for (int k = 0; k < 2; ++k) {
            const int nl = w + 8 * (t + k);
            ob[(size_t)nl * OUTF]      = resA[k];
            ob[(size_t)nl * OUTF + 32] = resB[k];
        }
    }
}

// ============================================================================
extern "C" void kernel_launch(void* const* d_in, const int* in_sizes, int n_in,
                              void* d_out, int out_size) {
    const float* x = (const float*)d_in[0];   // (32, 20000, 64)
    const float* V = (const float*)d_in[1];   // (20000, 16)
    const float* G = (const float*)d_in[2];   // (64, 64, 16, 16)
    float* out = (float*)d_out;               // (32, 20000, 64)

    k1_project<<<dim3(NCHUNK, BATCH), 256>>>(x, V);
    k1b_reduce<<<32, 256>>>();
    k2_mix<<<512, 256>>>(G);
    k3_expand<<<dim3(NCH3, BATCH), 256>>>(V, out);
}

// round 9
// speedup vs baseline: 1.6099x; 1.0227x over previous
#include <cuda_runtime.h>
#include <cstdint>

#define BATCH  32
#define NODES  20000
#define FEAT   64
#define OUTF   64
#define EIG    16

#define NCHUNK 25
#define MCHUNK (NODES / NCHUNK)   // 800
#define K1TILE 160                // V rows staged per k1 tile (5 tiles/chunk)
#define STRIP  (K1TILE / 8)       // 20 contiguous rows per warp per tile

#define NPB3   400                // nodes per k3 block
#define NCH3   (NODES / NPB3)     // 50

typedef unsigned long long ull;

// Scratch (device globals; no allocation allowed)
__device__ __align__(16) float zpart_g[BATCH * NCHUNK * FEAT * EIG]; // 3.3 MB
__device__ __align__(16) float z_g[BATCH * FEAT * EIG];              // 128 KB
__device__ __align__(16) float w_g[BATCH * OUTF * EIG];              // 128 KB

// ---- packed f32x2 helpers ----
__device__ __forceinline__ ull ffma2(ull a, ull b, ull c) {
    ull d;
    asm("fma.rn.f32x2 %0, %1, %2, %3;" : "=l"(d) : "l"(a), "l"(b), "l"(c));
    return d;
}
__device__ __forceinline__ ull fadd2(ull a, ull b) {
    ull d;
    asm("add.rn.f32x2 %0, %1, %2;" : "=l"(d) : "l"(a), "l"(b));
    return d;
}
__device__ __forceinline__ ull pack2(float x) {
    ull d;
    asm("mov.b64 %0, {%1, %1};" : "=l"(d) : "f"(x));
    return d;
}
__device__ __forceinline__ ull packab(float a, float b) {
    ull d;
    asm("mov.b64 %0, {%1, %2};" : "=l"(d) : "f"(a), "f"(b));
    return d;
}
__device__ __forceinline__ float hsum2(ull a) {
    float lo, hi;
    asm("mov.b64 {%0, %1}, %2;" : "=f"(lo), "=f"(hi) : "l"(a));
    return lo + hi;
}

// ============================================================================
// Kernel 1: zpart[b][chunk][i][e] = sum_{m in chunk} V[m,e] * x[b,m,i]
// grid (NCHUNK, BATCH), 256 thr = 8 warps. Warp w owns a contiguous STRIP of
// rows per tile; lane l owns i = 2l,2l+1; acc packed over e-pairs (16 f32x2).
// x loads SOFTWARE-PIPELINED: 5-deep ping-pong, next group prefetched before
// current group's FMAs (incl. cross-tile prefetch) -> LDG latency overlapped.
// ============================================================================
__global__ void __launch_bounds__(256, 3) k1_project(const float* __restrict__ x,
                                                     const float* __restrict__ V) {
    __shared__ __align__(16) ulonglong2 Vs[K1TILE][4];   // 10 KB
    __shared__ __align__(16) ull part[8][32][16];        // 32 KB

    const int tid  = threadIdx.x;
    const int lane = tid & 31;
    const int w    = tid >> 5;
    const int b    = blockIdx.y;
    const int m0   = blockIdx.x * MCHUNK;

    const float2* xb = (const float2*)(x + ((size_t)b * NODES + m0) * FEAT) + lane;
    const int lb = w * STRIP;          // this warp's local row base within a tile

    ull acc[16];
#pragma unroll
    for (int p = 0; p < 16; ++p) acc[p] = 0ULL;

    float2 bufA[5], bufB[5];
    // prologue: group 0 of tile 0
#pragma unroll
    for (int k = 0; k < 5; ++k) bufA[k] = xb[(size_t)(lb + k) * 32];

#define K1_PROC(MLB, BUF)                                                     \
    {                                                                         \
        _Pragma("unroll")                                                     \
        for (int k = 0; k < 5; ++k) {                                         \
            const int ml = (MLB) + k;                                         \
            ull xa = pack2(BUF[k].x);                                         \
            ull xc = pack2(BUF[k].y);                                         \
            ulonglong2 q0 = Vs[ml][0], q1 = Vs[ml][1];                        \
            ulonglong2 q2 = Vs[ml][2], q3 = Vs[ml][3];                        \
            acc[0]  = ffma2(q0.x, xa, acc[0]);                                \
            acc[1]  = ffma2(q0.y, xa, acc[1]);                                \
            acc[2]  = ffma2(q1.x, xa, acc[2]);                                \
            acc[3]  = ffma2(q1.y, xa, acc[3]);                                \
            acc[4]  = ffma2(q2.x, xa, acc[4]);                                \
            acc[5]  = ffma2(q2.y, xa, acc[5]);                                \
            acc[6]  = ffma2(q3.x, xa, acc[6]);                                \
            acc[7]  = ffma2(q3.y, xa, acc[7]);                                \
            acc[8]  = ffma2(q0.x, xc, acc[8]);                                \
            acc[9]  = ffma2(q0.y, xc, acc[9]);                                \
            acc[10] = ffma2(q1.x, xc, acc[10]);                               \
            acc[11] = ffma2(q1.y, xc, acc[11]);                               \
            acc[12] = ffma2(q2.x, xc, acc[12]);                               \
            acc[13] = ffma2(q2.y, xc, acc[13]);                               \
            acc[14] = ffma2(q3.x, xc, acc[14]);                               \
            acc[15] = ffma2(q3.y, xc, acc[15]);                               \
        }                                                                     \
    }

#pragma unroll 1
    for (int tb = 0; tb < MCHUNK; tb += K1TILE) {
        __syncthreads();   // previous tile's Vs reads complete
        // stage V tile (coalesced 16B loads)
        for (int idx = tid; idx < K1TILE * 4; idx += 256) {
            int ml = idx >> 2, p = idx & 3;
            Vs[ml][p] = ((const ulonglong2*)(V + (size_t)(m0 + tb + ml) * EIG))[p];
        }
        __syncthreads();

        // group 0 in bufA; prefetch g1 -> B, proc A; prefetch g2 -> A, proc B; ...
#pragma unroll
        for (int k = 0; k < 5; ++k) bufB[k] = xb[(size_t)(tb + lb + 5 + k) * 32];
        K1_PROC(lb + 0, bufA);
#pragma unroll
        for (int k = 0; k < 5; ++k) bufA[k] = xb[(size_t)(tb + lb + 10 + k) * 32];
        K1_PROC(lb + 5, bufB);
#pragma unroll
        for (int k = 0; k < 5; ++k) bufB[k] = xb[(size_t)(tb + lb + 15 + k) * 32];
        K1_PROC(lb + 10, bufA);
        const int nt = tb + K1TILE;
        if (nt < MCHUNK) {
#pragma unroll
            for (int k = 0; k < 5; ++k) bufA[k] = xb[(size_t)(nt + lb + k) * 32];
        }
        K1_PROC(lb + 15, bufB);
    }
#undef K1_PROC

    // dump per-warp partials, then flat deterministic sum over the 8 warps
#pragma unroll
    for (int p = 0; p < 16; ++p) part[w][lane][p] = acc[p];
    __syncthreads();

    {
        const int li = tid >> 3;            // ull-slot pair (2*tid, 2*tid+1)
        const int k  = (2 * tid) & 15;
        ulonglong2 r = *(const ulonglong2*)&part[0][li][k];
#pragma unroll
        for (int ww = 1; ww < 8; ++ww) {
            ulonglong2 s = *(const ulonglong2*)&part[ww][li][k];
            r.x = fadd2(r.x, s.x);
            r.y = fadd2(r.y, s.y);
        }
        ulonglong2* zp = (ulonglong2*)(zpart_g + ((size_t)b * NCHUNK + blockIdx.x) * (FEAT * EIG));
        zp[tid] = r;
    }
}

// ============================================================================
// Kernel 1b: z[b][i][e] = sum_c zpart[b][c][i][e]      grid 32 x 256
// ============================================================================
__global__ void __launch_bounds__(256) k1b_reduce() {
    int idx = blockIdx.x * 256 + threadIdx.x;
    int b = idx >> 8, q = idx & 255;
    const float4* zp = (const float4*)zpart_g;
    float4 s = make_float4(0.f, 0.f, 0.f, 0.f);
#pragma unroll
    for (int c = 0; c < NCHUNK; ++c) {
        float4 v = zp[((size_t)b * NCHUNK + c) * 256 + q];
        s.x += v.x; s.y += v.y; s.z += v.z; s.w += v.w;
    }
    ((float4*)z_g)[(size_t)b * 256 + q] = s;
}

// ============================================================================
// Kernel 2: w[b][j][e] = sum_{i,f} G[j,i,e,f] * z[b,i,f]
// One warp per (c = j*16+e, batch-group of 8).  grid 512 x 256
// ============================================================================
__global__ void __launch_bounds__(256) k2_mix(const float* __restrict__ G) {
    const int lane = threadIdx.x & 31;
    const int W    = blockIdx.x * 8 + (threadIdx.x >> 5);
    const int c    = W >> 2;
    const int bg   = W & 3;
    const int j    = c >> 4;
    const int e    = c & 15;

    const float4* Gp = (const float4*)(G + (size_t)j * (FEAT * EIG * EIG) + (size_t)e * EIG);
    const float4* zb = (const float4*)z_g;
    const int i0 = lane >> 2, fq = lane & 3;

    float acc[8];
#pragma unroll
    for (int r = 0; r < 8; ++r) acc[r] = 0.f;

#pragma unroll
    for (int s = 0; s < 8; ++s) {
        int i  = s * 8 + i0;
        float4 g = Gp[(size_t)i * 64 + fq];
        int kq = i * 4 + fq;
#pragma unroll
        for (int r = 0; r < 8; ++r) {
            float4 zv = zb[(size_t)(bg * 8 + r) * 256 + kq];
            acc[r] = fmaf(g.x, zv.x, fmaf(g.y, zv.y, fmaf(g.z, zv.z, fmaf(g.w, zv.w, acc[r]))));
        }
    }
#pragma unroll
    for (int r = 0; r < 8; ++r) {
#pragma unroll
        for (int off = 16; off; off >>= 1)
            acc[r] += __shfl_xor_sync(0xffffffffu, acc[r], off);
    }
    if (lane == 0) {
#pragma unroll
        for (int r = 0; r < 8; ++r)
            w_g[(size_t)(bg * 8 + r) * 1024 + c] = acc[r];
    }
}

// ============================================================================
// Kernel 3: out[b,n,j] = sum_e V[n,e] * w[b,j,e]
// grid (NCH3, BATCH), 256 thr = 8 warps. Warp w owns nodes n0+w+8t;
// lane l owns j = l and j = l+32. Accumulate packed over e-PAIRS; V staged
// non-duplicated (4 LDS.128/node). NPB3=400 amortizes staging over a long loop.
// ============================================================================
__global__ void __launch_bounds__(256, 4) k3_expand(const float* __restrict__ V,
                                                    float* __restrict__ out) {
    __shared__ __align__(16) ull Vp[NPB3][8];      // (V[e],V[e+1]) pairs, 25 KB
    __shared__ float wsm[OUTF * 17];               // padded rows, 4.25 KB

    const int tid  = threadIdx.x;
    const int lane = tid & 31;
    const int w    = tid >> 5;
    const int b    = blockIdx.y;
    const int n0   = blockIdx.x * NPB3;

    // stage w[b] with row padding 17 (bank-conflict-free scalar reads)
    for (int idx = tid; idx < OUTF * EIG; idx += 256) {
        int j = idx >> 4, e = idx & 15;
        wsm[j * 17 + e] = w_g[(size_t)b * (OUTF * EIG) + idx];
    }
    // stage V rows as natural f32x2 pairs (plain contiguous copy, 16B loads)
    for (int idx = tid; idx < NPB3 * 4; idx += 256) {
        ((ulonglong2*)Vp)[idx] = ((const ulonglong2*)(V + (size_t)n0 * EIG))[idx];
    }
    __syncthreads();

    // per-lane w registers packed over e-pairs, for j=lane and j=lane+32
    ull wra[8], wrb[8];
#pragma unroll
    for (int p = 0; p < 8; ++p) {
        wra[p] = packab(wsm[lane * 17 + 2 * p], wsm[lane * 17 + 2 * p + 1]);
        wrb[p] = packab(wsm[(lane + 32) * 17 + 2 * p], wsm[(lane + 32) * 17 + 2 * p + 1]);
    }

    float* ob = out + ((size_t)b * NODES + n0) * OUTF + lane;

#pragma unroll 1
    for (int t = 0; t < NPB3 / 8; t += 2) {
        float resA[2], resB[2];
#pragma unroll
        for (int k = 0; k < 2; ++k) {
            const int nl = w + 8 * (t + k);
            const ulonglong2* vd = (const ulonglong2*)Vp[nl];
            ulonglong2 p0 = vd[0], p1 = vd[1], p2 = vd[2], p3 = vd[3];
            ull a = ffma2(p0.x, wra[0], 0ULL);
            ull c = ffma2(p0.y, wra[1], 0ULL);
            a = ffma2(p1.x, wra[2], a);
            c = ffma2(p1.y, wra[3], c);
            a = ffma2(p2.x, wra[4], a);
            c = ffma2(p2.y, wra[5], c);
            a = ffma2(p3.x, wra[6], a);
            c = ffma2(p3.y, wra[7], c);
            resA[k] = hsum2(fadd2(a, c));
            ull a2 = ffma2(p0.x, wrb[0], 0ULL);
            ull c2 = ffma2(p0.y, wrb[1], 0ULL);
            a2 = ffma2(p1.x, wrb[2], a2);
            c2 = ffma2(p1.y, wrb[3], c2);
            a2 = ffma2(p2.x, wrb[4], a2);
            c2 = ffma2(p2.y, wrb[5], c2);
            a2 = ffma2(p3.x, wrb[6], a2);
            c2 = ffma2(p3.y, wrb[7], c2);
            resB[k] = hsum2(fadd2(a2, c2));
        }
#pragma unroll
        for (int k = 0; k < 2; ++k) {
            const int nl = w + 8 * (t + k);
            ob[(size_t)nl * OUTF]      = resA[k];
            ob[(size_t)nl * OUTF + 32] = resB[k];
        }
    }
}

// ============================================================================
extern "C" void kernel_launch(void* const* d_in, const int* in_sizes, int n_in,
                              void* d_out, int out_size) {
    const float* x = (const float*)d_in[0];   // (32, 20000, 64)
    const float* V = (const float*)d_in[1];   // (20000, 16)
    const float* G = (const float*)d_in[2];   // (64, 64, 16, 16)
    float* out = (float*)d_out;               // (32, 20000, 64)

    k1_project<<<dim3(NCHUNK, BATCH), 256>>>(x, V);
    k1b_reduce<<<32, 256>>>();
    k2_mix<<<512, 256>>>(G);
    k3_expand<<<dim3(NCH3, BATCH), 256>>>(V, out);
}